// round 13
// baseline (speedup 1.0000x reference)
#include <cuda_runtime.h>
#include <math.h>
#include <stdint.h>
#include <stddef.h>

#define MAXN 4

// ---------------- scratch: device globals ----------------
__device__ float g_tmp  [(size_t)MAXN*32*256*256];
__device__ float g_buf1 [(size_t)MAXN*32*128*128];
__device__ float g_buf3 [(size_t)MAXN*128*64*64];
__device__ float g_buf5 [(size_t)MAXN*512*32*32];
__device__ float g_buf6 [(size_t)MAXN*256*32*32];
__device__ float g_buf9 [(size_t)MAXN*128*64*64];
__device__ float g_buf12[(size_t)MAXN*64*128*128];
__device__ float g_cat1 [(size_t)MAXN*48*256*256];
__device__ float g_cat2 [(size_t)MAXN*128*128*128];
__device__ float g_cat3 [(size_t)MAXN*512*64*64];

// conv weights, layout [cin][25][Cout]
__device__ float g_wc0 [3*25*16];
__device__ float g_wc1a[16*25*32];
__device__ float g_wc1b[32*25*64];
__device__ float g_wc2a[64*25*128];
__device__ float g_wc2b[128*25*256];
__device__ float g_wc3a[256*25*512];
__device__ float g_wc3b[512*25*256];
__device__ float g_wc5 [512*25*128];
__device__ float g_wc7 [128*25*64];
__device__ float g_wc10[48*25*16];
// fused deconv weights: [Cin][25 taps][Cout]
__device__ float g_wdf4[256*25*256];
__device__ float g_wdf6[128*25*64];
__device__ float g_wdf8[64*25*32];
__device__ float g_b4s[256];
__device__ float g_b6s[64];
__device__ float g_b8s[32];

// ---------------- helpers ----------------
__device__ __forceinline__ unsigned long long pack2(float a, float b)
{
    unsigned long long r;
    asm("mov.b64 %0, {%1, %2};" : "=l"(r) : "r"(__float_as_uint(a)), "r"(__float_as_uint(b)));
    return r;
}
__device__ __forceinline__ void ffma2(unsigned long long& d, unsigned long long a, unsigned long long b)
{
    asm("fma.rn.f32x2 %0, %1, %2, %0;" : "+l"(d) : "l"(a), "l"(b));
}
__device__ __forceinline__ float2 unpack2(unsigned long long v)
{
    unsigned int lo, hi;
    asm("mov.b64 {%0, %1}, %2;" : "=r"(lo), "=r"(hi) : "l"(v));
    float2 f; f.x = __uint_as_float(lo); f.y = __uint_as_float(hi);
    return f;
}
__device__ __forceinline__ uint32_t saddr(const void* p)
{
    return (uint32_t)__cvta_generic_to_shared(p);
}
__device__ __forceinline__ void cpa4(uint32_t dst, const float* src, bool ok)
{
    int sz = ok ? 4 : 0;
    asm volatile("cp.async.ca.shared.global [%0], [%1], 4, %2;" :: "r"(dst), "l"(src), "r"(sz) : "memory");
}
__device__ __forceinline__ void cpa16(uint32_t dst, const float* src, bool ok)
{
    int sz = ok ? 16 : 0;
    asm volatile("cp.async.cg.shared.global [%0], [%1], 16, %2;" :: "r"(dst), "l"(src), "r"(sz) : "memory");
}
#define CP_COMMIT() asm volatile("cp.async.commit_group;" ::: "memory")
#define CP_WAIT0()  asm volatile("cp.async.wait_group 0;" ::: "memory")

__device__ __forceinline__ float route_f(int oh, int ow, int H, int W, float t1, float s2)
{
    int rlo = oh - 2 > 0 ? oh - 2 : 0;
    int rhi = oh + 2 < H - 1 ? oh + 2 : H - 1;
    int clo = ow - 2 > 0 ? ow - 2 : 0;
    int chi = ow + 2 < W - 1 ? ow + 2 : W - 1;
    float cnt = (float)((rhi - rlo + 1) * (chi - clo + 1));
    float r = 1.f / (t1 * cnt);
    float n2 = r * r * s2;
    return r * n2 / ((1.f + n2) * sqrtf(n2 + 1e-9f));
}

// ---------------- fused weight prep ----------------
struct PrepC {
    const float* src[10]; float* dst[10];
    int t0[10], Cout[10], z0[10];
};
__global__ void k_prep_conv(PrepC a)
{
    int task = blockIdx.y;
    int t0 = a.t0[task], Cout = a.Cout[task], z0 = a.z0[task];
    int total = t0 * z0 * 25 * Cout;
    int i = blockIdx.x * 256 + threadIdx.x;
    if (i >= total) return;
    int o = i % Cout; int r = i / Cout;
    int k = r % 25; r /= 25;
    int z = r % z0; int t = r / z0;
    a.dst[task][i] = a.src[task][((size_t)(t * Cout + o) * z0 + z) * 25 + k];
}

struct PrepD {
    const float* src[6]; float* dst[6];
    int Cin[6], Cout[6], t0[6], kind[6];
};
__global__ void k_prep_dec(PrepD a)
{
    int task = blockIdx.y;
    int i = blockIdx.x * 256 + threadIdx.x;
    int Cout = a.Cout[task];
    if (a.kind[task] == 1) {
        if (i >= Cout) return;
        float s = 0.f;
        for (int t = 0; t < a.t0[task]; ++t) s += a.src[task][t * Cout + i];
        a.dst[task][i] = s;
        return;
    }
    int Cin = a.Cin[task];
    int total = Cin * 25 * Cout;
    if (i >= total) return;
    int o = i % Cout; int r = i / Cout;
    int tap = r % 25; int c = r / 25;
    int ph, pw, dh, dw;
    if (tap < 9)       { ph = 0; pw = 0; dh = tap / 3 - 1;       dw = tap % 3 - 1; }
    else if (tap < 15) { int t = tap - 9;  ph = 0; pw = 1; dh = t / 2 - 1; dw = t % 2; }
    else if (tap < 21) { int t = tap - 15; ph = 1; pw = 0; dh = t / 3;     dw = t % 3 - 1; }
    else               { int t = tap - 21; ph = 1; pw = 1; dh = t / 2;     dw = t % 2; }
    int kh = 2 * (dh + (ph ? 0 : 1)) + ph;
    int kw = 2 * (dw + (pw ? 0 : 1)) + pw;
    a.dst[task][i] = a.src[task][((size_t)c * Cout + o) * 25 + (4 - kh) * 5 + (4 - kw)];
}

// ---------------- cp.async pipelined tiled conv, optional fused squash ----------------
template<int KH, int KW, int S, int TOC, int NC, int Z1, bool FINAL>
__global__ __launch_bounds__(256, 2)
void conv_tiled(const float* __restrict__ x, const float* __restrict__ wgt,
                float* __restrict__ y,
                int Cin, int Hin, int Win, int CinTot, int cin0,
                int Cout, int Hout, int Wout, int padh, int padw,
                int CoutTot, int oc0, int t1i, int nOcTiles)
{
    constexpr int TW = 32, TH = 8, PIX = 8;
    constexpr int WG = 4;
    constexpr int OCT = TOC / 8;
    constexpr int NPAIR = OCT / 2;
    constexpr int XW = (TW - 1) * S + KW;
    constexpr int XH = (TH - 1) * S + KH;
    constexpr int XWP = (XW & 1) ? XW : XW + 1;
    constexpr int KK = KH * KW;
    constexpr int SPAN = (PIX - 1) * S + KW;
    constexpr int XTOT = NC * XH * XW;
    constexpr int WTOT = NC * KK * TOC;
    constexpr int XCNT = (XTOT + 255) / 256;
    constexpr int WQ   = WTOT / 4;
    constexpr int WQCNT = (WQ + 255) / 256;
    constexpr int SXSZ = 2 * NC * XH * XWP;
    static_assert(NPAIR >= 1, "need oc pairs");
    static_assert(Z1 == 0 || (Z1 % OCT == 0 && TOC % Z1 == 0), "z1 grouping");
    static_assert(Z1 == 0 || SXSZ + 2 * WTOT >= 8 * 32 * PIX, "ps overlay fits");

    __shared__ __align__(16) float smem_all[SXSZ + 2 * WTOT];

    const int tid = threadIdx.x;
    const int owg = tid % WG;
    const int ohh = (tid / WG) % TH;
    const int ocg = tid >> 5;
    const int lane = tid & 31;

    const int wt = blockIdx.x, ht = blockIdx.y;
    const int octile = blockIdx.z % nOcTiles;
    const int n      = blockIdx.z / nOcTiles;

    const int ocb = octile * TOC;
    const int oh0 = ht * TH, ow0 = wt * TW;
    const int ih0 = oh0 * S - padh;
    const int iw0 = ow0 * S - padw;
    const size_t HWin = (size_t)Hin * Win;

    const float* xn = x + ((size_t)n * CinTot + cin0) * HWin;
    const float* wb = wgt + ocb;
    const int nCh = (Cin + NC - 1) / NC;

    const uint32_t sxa = saddr(smem_all);
    const uint32_t swa = sxa + SXSZ * 4;

    unsigned long long acc[NPAIR][PIX];
    #pragma unroll
    for (int p = 0; p < NPAIR; ++p)
        #pragma unroll
        for (int i = 0; i < PIX; ++i) acc[p][i] = 0ull;

    auto issue = [&](int ch, int buf) {
        #pragma unroll
        for (int j = 0; j < XCNT; ++j) {
            int g = tid + j * 256;
            if (g < XTOT) {
                int c = g / (XH * XW), r = g % (XH * XW);
                int rr = r / XW, cc = r % XW;
                int ci = ch * NC + c;
                int hi = ih0 + rr, wi = iw0 + cc;
                bool ok = (ci < Cin) && (hi >= 0) && (hi < Hin) && (wi >= 0) && (wi < Win);
                const float* src = ok ? xn + (size_t)ci * HWin + (size_t)hi * Win + wi : xn;
                cpa4(sxa + (uint32_t)(buf * (NC * XH * XWP) + c * (XH * XWP) + rr * XWP + cc) * 4,
                     src, ok);
            }
        }
        #pragma unroll
        for (int j = 0; j < WQCNT; ++j) {
            int q = tid + j * 256;
            if (q < WQ) {
                int idx = q * 4;
                int c = idx / (KK * TOC), r = idx % (KK * TOC);
                int kk = r / TOC, oc = r % TOC;
                int ci = ch * NC + c;
                bool ok = ci < Cin;
                const float* src = ok ? wb + ((size_t)ci * KK + kk) * Cout + oc : wgt;
                cpa16(swa + (uint32_t)(buf * WTOT + idx) * 4, src, ok);
            }
        }
        CP_COMMIT();
    };

    issue(0, 0);

    const int xbase = (ohh * S) * XWP + owg * PIX * S;

    for (int ch = 0; ch < nCh; ++ch) {
        CP_WAIT0();
        __syncthreads();
        if (ch + 1 < nCh) issue(ch + 1, (ch + 1) & 1);

        const float* sxb = smem_all + (ch & 1) * (NC * XH * XWP);
        const float* swb = smem_all + SXSZ + (ch & 1) * WTOT;
        #pragma unroll 1
        for (int c = 0; c < NC; ++c) {
            const float* sxc = sxb + c * (XH * XWP);
            const float* swc = swb + c * (KK * TOC) + ocg * OCT;
            #pragma unroll
            for (int kh = 0; kh < KH; ++kh) {
                unsigned long long xd[SPAN];
                #pragma unroll
                for (int i = 0; i < SPAN; ++i) {
                    float v = sxc[xbase + kh * XWP + i];
                    xd[i] = pack2(v, v);
                }
                #pragma unroll
                for (int kw = 0; kw < KW; ++kw) {
                    const float* wp = swc + (kh * KW + kw) * TOC;
                    if (NPAIR == 2) {
                        ulonglong2 wv2 = *(const ulonglong2*)wp;
                        #pragma unroll
                        for (int i = 0; i < PIX; ++i) {
                            ffma2(acc[0][i], xd[i * S + kw], wv2.x);
                            ffma2(acc[1][i], xd[i * S + kw], wv2.y);
                        }
                    } else {
                        #pragma unroll
                        for (int p = 0; p < NPAIR; ++p) {
                            unsigned long long wv = *(const unsigned long long*)(wp + 2 * p);
                            #pragma unroll
                            for (int i = 0; i < PIX; ++i)
                                ffma2(acc[p][i], xd[i * S + kw], wv);
                        }
                    }
                }
            }
        }
    }

    const int oh = oh0 + ohh;

    if (Z1 == 0) {
        #pragma unroll
        for (int p = 0; p < NPAIR; ++p) {
            int oca = ocb + ocg * OCT + 2 * p;
            float* y0 = y + (((size_t)n * CoutTot + oc0 + oca) * Hout + oh) * Wout;
            float* y1 = y0 + (size_t)Hout * Wout;
            #pragma unroll
            for (int i = 0; i < PIX; ++i) {
                int ow = ow0 + owg * PIX + i;
                float2 v = unpack2(acc[p][i]);
                y0[ow] = v.x;
                y1[ow] = v.y;
            }
        }
    } else {
        __syncthreads();
        float* ps = smem_all;
        #pragma unroll
        for (int i = 0; i < PIX; ++i) {
            float s = 0.f;
            #pragma unroll
            for (int p = 0; p < NPAIR; ++p) {
                float2 v = unpack2(acc[p][i]);
                s += v.x * v.x + v.y * v.y;
            }
            ps[ocg * 256 + i * 32 + lane] = s;
        }
        __syncthreads();
        constexpr int GPERZ = (Z1 > 0) ? Z1 / OCT : 1;
        const int g0 = (ocg / GPERZ) * GPERZ;
        const float t1f = (float)t1i;
        #pragma unroll
        for (int i = 0; i < PIX; ++i) {
            int ow = ow0 + owg * PIX + i;
            float s2 = 0.f;
            #pragma unroll
            for (int g = 0; g < GPERZ; ++g) s2 += ps[(g0 + g) * 256 + i * 32 + lane];
            float f = route_f(oh, ow, Hout, Wout, t1f, s2);
            if (FINAL) {
                if (ocg == 0)
                    y[((size_t)n * Hout + oh) * Wout + ow] = sqrtf(f * f * s2 + 1e-9f);
            } else {
                #pragma unroll
                for (int p = 0; p < NPAIR; ++p) {
                    int oca = ocb + ocg * OCT + 2 * p;
                    float2 v = unpack2(acc[p][i]);
                    y[(((size_t)n * CoutTot + oc0 + oca) * Hout + oh) * Wout + ow] = f * v.x;
                    y[(((size_t)n * CoutTot + oc0 + oca + 1) * Hout + oh) * Wout + ow] = f * v.y;
                }
            }
        }
    }
}

// ---------------- fused 4-parity deconv with cp.async, optional squash ----------------
template<int TOC, int Z1, int NC>
__global__ __launch_bounds__(256, 2)
void deconv_tiled(const float* __restrict__ x, const float* __restrict__ wgt,
                  const float* __restrict__ bias, float* __restrict__ y,
                  int Cin, int H, int W, int Cout, int CoutTot, int t1i, int nOcTiles)
{
    constexpr int TW = 32, TH = 8, PIX = 8;
    constexpr int WG = 4;
    constexpr int OCT = TOC / 8;
    static_assert(OCT == 2, "deconv uses OCT=2");
    constexpr int XW = TW + 2, XH = TH + 2, XWP = XW + 1;
    constexpr int XTOT = NC * XH * XW;
    constexpr int WTOT = NC * 25 * TOC;
    constexpr int XCNT = (XTOT + 255) / 256;
    constexpr int WQ   = WTOT / 4;
    constexpr int WQCNT = (WQ + 255) / 256;
    constexpr int SXSZ = 2 * NC * XH * XWP;
    constexpr int SMSZ = (SXSZ + 2 * WTOT) > 2048 ? (SXSZ + 2 * WTOT) : 2048;

    __shared__ __align__(16) float smem_all[SMSZ];

    const int tid = threadIdx.x;
    const int owg = tid % WG;
    const int ohh = (tid / WG) % TH;
    const int ocg = tid >> 5;
    const int lane = tid & 31;

    const int wt = blockIdx.x, ht = blockIdx.y;
    const int octile = blockIdx.z % nOcTiles;
    const int n      = blockIdx.z / nOcTiles;

    const int ocb = octile * TOC;
    const int oh0 = ht * TH, ow0 = wt * TW;
    const int ih0 = oh0 - 1, iw0 = ow0 - 1;
    const size_t HWin = (size_t)H * W;
    const int yH = 2 * H, yW = 2 * W;

    const int oca = ocb + ocg * OCT;
    unsigned long long bi = pack2(bias[oca], bias[oca + 1]);
    unsigned long long acc[4][PIX];
    #pragma unroll
    for (int par = 0; par < 4; ++par)
        #pragma unroll
        for (int i = 0; i < PIX; ++i) acc[par][i] = bi;

    const float* xn = x + (size_t)n * Cin * HWin;
    const float* wb = wgt + ocb;
    const int nCh = (Cin + NC - 1) / NC;

    const uint32_t sxa = saddr(smem_all);
    const uint32_t swa = sxa + SXSZ * 4;

    auto issue = [&](int ch, int buf) {
        #pragma unroll
        for (int j = 0; j < XCNT; ++j) {
            int g = tid + j * 256;
            if (g < XTOT) {
                int c = g / (XH * XW), r = g % (XH * XW);
                int rr = r / XW, cc = r % XW;
                int ci = ch * NC + c;
                int hi = ih0 + rr, wi = iw0 + cc;
                bool ok = (ci < Cin) && (hi >= 0) && (hi < H) && (wi >= 0) && (wi < W);
                const float* src = ok ? xn + (size_t)ci * HWin + (size_t)hi * W + wi : xn;
                cpa4(sxa + (uint32_t)(buf * (NC * XH * XWP) + c * (XH * XWP) + rr * XWP + cc) * 4,
                     src, ok);
            }
        }
        #pragma unroll
        for (int j = 0; j < WQCNT; ++j) {
            int q = tid + j * 256;
            if (q < WQ) {
                int idx = q * 4;
                int c = idx / (25 * TOC), r = idx % (25 * TOC);
                int tap = r / TOC, oc = r % TOC;
                int ci = ch * NC + c;
                bool ok = ci < Cin;
                const float* src = ok ? wb + ((size_t)ci * 25 + tap) * Cout + oc : wgt;
                cpa16(swa + (uint32_t)(buf * WTOT + idx) * 4, src, ok);
            }
        }
        CP_COMMIT();
    };

    issue(0, 0);

    for (int ch = 0; ch < nCh; ++ch) {
        CP_WAIT0();
        __syncthreads();
        if (ch + 1 < nCh) issue(ch + 1, (ch + 1) & 1);

        const float* sxb = smem_all + (ch & 1) * (NC * XH * XWP);
        const float* swb = smem_all + SXSZ + (ch & 1) * WTOT;
        #pragma unroll 1
        for (int c = 0; c < NC; ++c) {
            const float* sxc = sxb + c * (XH * XWP);
            const float* swc = swb + c * (25 * TOC) + ocg * OCT;
            #pragma unroll
            for (int dh = -1; dh <= 1; ++dh) {
                unsigned long long xd[PIX + 2];
                const int rbase = (ohh + 1 + dh) * XWP + owg * PIX;
                #pragma unroll
                for (int j = 0; j < PIX + 2; ++j) {
                    float v = sxc[rbase + j];
                    xd[j] = pack2(v, v);
                }
                #pragma unroll
                for (int dw = -1; dw <= 1; ++dw) {
                    unsigned long long wv = *(const unsigned long long*)
                        (swc + ((dh + 1) * 3 + (dw + 1)) * TOC);
                    #pragma unroll
                    for (int i = 0; i < PIX; ++i)
                        ffma2(acc[0][i], xd[i + dw + 1], wv);
                }
                #pragma unroll
                for (int dw = 0; dw <= 1; ++dw) {
                    unsigned long long wv = *(const unsigned long long*)
                        (swc + (9 + (dh + 1) * 2 + dw) * TOC);
                    #pragma unroll
                    for (int i = 0; i < PIX; ++i)
                        ffma2(acc[1][i], xd[i + dw + 1], wv);
                }
                if (dh >= 0) {
                    #pragma unroll
                    for (int dw = -1; dw <= 1; ++dw) {
                        unsigned long long wv = *(const unsigned long long*)
                            (swc + (15 + dh * 3 + (dw + 1)) * TOC);
                        #pragma unroll
                        for (int i = 0; i < PIX; ++i)
                            ffma2(acc[2][i], xd[i + dw + 1], wv);
                    }
                    #pragma unroll
                    for (int dw = 0; dw <= 1; ++dw) {
                        unsigned long long wv = *(const unsigned long long*)
                            (swc + (21 + dh * 2 + dw) * TOC);
                        #pragma unroll
                        for (int i = 0; i < PIX; ++i)
                            ffma2(acc[3][i], xd[i + dw + 1], wv);
                    }
                }
            }
        }
    }

    if (Z1 == 0) {
        #pragma unroll
        for (int par = 0; par < 4; ++par) {
            const int ph = par >> 1, pw = par & 1;
            const int oh = 2 * (oh0 + ohh) + ph;
            float* y0 = y + (((size_t)n * CoutTot + oca) * yH + oh) * yW;
            float* y1 = y0 + (size_t)yH * yW;
            #pragma unroll
            for (int i = 0; i < PIX; ++i) {
                int ow = 2 * (ow0 + owg * PIX + i) + pw;
                float2 v = unpack2(acc[par][i]);
                y0[ow] = v.x;
                y1[ow] = v.y;
            }
        }
    } else {
        static_assert(Z1 == 0 || Z1 == TOC, "deconv squash: one group per tile");
        __syncthreads();
        float* ps = smem_all;
        const float t1f = (float)t1i;
        #pragma unroll 1
        for (int par = 0; par < 4; ++par) {
            const int ph = par >> 1, pw = par & 1;
            const int oh = 2 * (oh0 + ohh) + ph;
            #pragma unroll
            for (int i = 0; i < PIX; ++i) {
                float2 v = unpack2(acc[par][i]);
                ps[ocg * 256 + i * 32 + lane] = v.x * v.x + v.y * v.y;
            }
            __syncthreads();
            #pragma unroll
            for (int i = 0; i < PIX; ++i) {
                int ow = 2 * (ow0 + owg * PIX + i) + pw;
                float s2 = 0.f;
                #pragma unroll
                for (int g = 0; g < 8; ++g) s2 += ps[g * 256 + i * 32 + lane];
                float f = route_f(oh, ow, yH, yW, t1f, s2);
                float2 v = unpack2(acc[par][i]);
                y[(((size_t)n * CoutTot + oca) * yH + oh) * yW + ow] = f * v.x;
                y[(((size_t)n * CoutTot + oca + 1) * yH + oh) * yW + ow] = f * v.y;
            }
            __syncthreads();
        }
    }
}

// ---------------- standalone squash (z1 > tile) ----------------
__global__ void k_squash(const float* __restrict__ x, float* __restrict__ y,
                         int N, int t1, int z1, int H, int W, int CoutTot, int ch0)
{
    int idx = blockIdx.x * blockDim.x + threadIdx.x;
    int total = N * t1 * H * W;
    if (idx >= total) return;
    int w = idx % W; int t = idx / W;
    int h = t % H;   t /= H;
    int tt = t % t1; int n = t / t1;

    size_t HW = (size_t)H * W;
    const float* xp = x + ((size_t)(n * t1 + tt) * z1) * HW + (size_t)h * W + w;
    float s2 = 0.f;
    for (int c = 0; c < z1; ++c) { float v = xp[c * HW]; s2 += v * v; }
    float f = route_f(h, w, H, W, (float)t1, s2);
    float* yp = y + ((size_t)n * CoutTot + ch0 + tt * z1) * HW + (size_t)h * W + w;
    for (int c = 0; c < z1; ++c) yp[c * HW] = f * xp[c * HW];
}

// ---------------- host dispatch ----------------
template<int KH, int KW, int S, int TOC, int Z1, bool FINAL>
static void launch_conv(const float* x, const float* w, float* y,
                        int N, int Cin, int Hin, int Win, int CinTot, int cin0,
                        int Cout, int Hout, int Wout, int padh, int padw,
                        int CoutTot, int oc0, int t1)
{
    constexpr int NC = (S == 2) ? 2 : 4;
    int nOcT = (Cout + TOC - 1) / TOC;
    dim3 grid((Wout + 31) / 32, (Hout + 7) / 8, N * nOcT);
    conv_tiled<KH, KW, S, TOC, NC, Z1, FINAL><<<grid, 256>>>(
        x, w, y, Cin, Hin, Win, CinTot, cin0,
        Cout, Hout, Wout, padh, padw, CoutTot, oc0, t1, nOcT);
}

template<int Z1>
static void launch_deconv(const float* x, const float* w, const float* b, float* y,
                          int N, int Cin, int H, int W, int Cout, int CoutTot, int t1)
{
    constexpr int TOC = 16;
    int nOcT = Cout / TOC;
    dim3 grid(W / 32, H / 8, N * nOcT);
    deconv_tiled<TOC, Z1, 4><<<grid, 256>>>(x, w, b, y, Cin, H, W, Cout, CoutTot, t1, nOcT);
}

static float* sym(const void* s)
{
    void* p = nullptr;
    cudaGetSymbolAddress(&p, (const void*)s);
    return (float*)p;
}

extern "C" void kernel_launch(void* const* d_in, const int* in_sizes, int n_in,
                              void* d_out, int out_size)
{
    const float* x    = (const float*)d_in[0];
    const float* w0   = (const float*)d_in[1];
    const float* w1a  = (const float*)d_in[2];
    const float* w1b  = (const float*)d_in[3];
    const float* w2a  = (const float*)d_in[4];
    const float* w2b  = (const float*)d_in[5];
    const float* w3a  = (const float*)d_in[6];
    const float* w3b  = (const float*)d_in[7];
    const float* w4   = (const float*)d_in[8];
    const float* b4   = (const float*)d_in[9];
    const float* w5   = (const float*)d_in[10];
    const float* w6   = (const float*)d_in[11];
    const float* b6   = (const float*)d_in[12];
    const float* w7   = (const float*)d_in[13];
    const float* w8   = (const float*)d_in[14];
    const float* b8   = (const float*)d_in[15];
    const float* w10  = (const float*)d_in[16];
    float* out = (float*)d_out;
    (void)n_in; (void)out_size;

    const int N = in_sizes[0] / (3 * 256 * 256);

    float* tmp   = sym(&g_tmp);
    float* buf1  = sym(&g_buf1);
    float* buf3  = sym(&g_buf3);
    float* buf5  = sym(&g_buf5);
    float* buf6  = sym(&g_buf6);
    float* buf9  = sym(&g_buf9);
    float* buf12 = sym(&g_buf12);
    float* cat1  = sym(&g_cat1);
    float* cat2  = sym(&g_cat2);
    float* cat3  = sym(&g_cat3);
    float* wc0   = sym(&g_wc0);
    float* wc1a  = sym(&g_wc1a);
    float* wc1b  = sym(&g_wc1b);
    float* wc2a  = sym(&g_wc2a);
    float* wc2b  = sym(&g_wc2b);
    float* wc3a  = sym(&g_wc3a);
    float* wc3b  = sym(&g_wc3b);
    float* wc5   = sym(&g_wc5);
    float* wc7   = sym(&g_wc7);
    float* wc10  = sym(&g_wc10);
    float* wdf4  = sym(&g_wdf4);
    float* wdf6  = sym(&g_wdf6);
    float* wdf8  = sym(&g_wdf8);
    float* b4s   = sym(&g_b4s);
    float* b6s   = sym(&g_b6s);
    float* b8s   = sym(&g_b8s);

    // ---- weight prep: 2 fused launches ----
    {
        PrepC pc;
        const float* srcs[10] = {w0, w1a, w1b, w2a, w2b, w3a, w3b, w5, w7, w10};
        float*       dsts[10] = {wc0, wc1a, wc1b, wc2a, wc2b, wc3a, wc3b, wc5, wc7, wc10};
        int t0s[10]   = {1, 1, 2, 4, 4, 8, 8, 16, 8, 3};
        int couts[10] = {16, 32, 64, 128, 256, 512, 256, 128, 64, 16};
        int z0s[10]   = {3, 16, 16, 16, 32, 32, 64, 32, 16, 16};
        int maxTot = 0;
        for (int i = 0; i < 10; ++i) {
            pc.src[i] = srcs[i]; pc.dst[i] = dsts[i];
            pc.t0[i] = t0s[i]; pc.Cout[i] = couts[i]; pc.z0[i] = z0s[i];
            int tot = t0s[i] * couts[i] * z0s[i] * 25;
            if (tot > maxTot) maxTot = tot;
        }
        dim3 g((maxTot + 255) / 256, 10);
        k_prep_conv<<<g, 256>>>(pc);
    }
    {
        PrepD pd;
        const float* wsrc[3] = {w4, w6, w8};
        float*       wdst[3] = {wdf4, wdf6, wdf8};
        int cins[3]  = {256, 128, 64};
        int couts[3] = {256, 64, 32};
        int t0s[3]   = {8, 4, 4};
        const float* bsrc[3] = {b4, b6, b8};
        float*       bdst[3] = {b4s, b6s, b8s};
        int maxTot = 0;
        for (int d = 0; d < 3; ++d) {
            pd.src[d] = wsrc[d]; pd.dst[d] = wdst[d];
            pd.Cin[d] = cins[d]; pd.Cout[d] = couts[d]; pd.t0[d] = t0s[d]; pd.kind[d] = 0;
            int tot = cins[d] * 25 * couts[d];
            if (tot > maxTot) maxTot = tot;
            pd.src[3 + d] = bsrc[d]; pd.dst[3 + d] = bdst[d];
            pd.Cin[3 + d] = 0; pd.Cout[3 + d] = couts[d]; pd.t0[3 + d] = t0s[d]; pd.kind[3 + d] = 1;
        }
        dim3 g((maxTot + 255) / 256, 6);
        k_prep_dec<<<g, 256>>>(pd);
    }

    // ---- forward pass (R9 schedule; only deconv NC 2->4 changed) ----
    // conv1 -> cat1 [32..48)  (skip1, raw)
    launch_conv<5,5,1,16,0,false>(x, wc0, cat1, N, 3,256,256, 3,0, 16,256,256, 2,2, 48,32, 0);
    // caps1a (s=2, t1=2 z1=16) fused squash -> buf1
    launch_conv<5,5,2,32,16,false>(cat1, wc1a, buf1, N, 16,256,256, 48,32, 32,128,128, 2,2, 32,0, 2);
    // caps1b (t1=4 z1=16) fused -> cat2 [64..128)
    launch_conv<5,5,1,32,16,false>(buf1, wc1b, cat2, N, 32,128,128, 32,0, 64,128,128, 2,2, 128,64, 4);
    // caps2a (s=2, t1=4 z1=32) fused -> buf3
    launch_conv<5,5,2,32,32,false>(cat2, wc2a, buf3, N, 64,128,128, 128,64, 128,64,64, 2,2, 128,0, 4);
    // caps2b (t1=8 z1=32) fused -> cat3 [256..512)
    launch_conv<5,5,1,32,32,false>(buf3, wc2b, cat3, N, 128,64,64, 128,0, 256,64,64, 2,2, 512,256, 8);
    // caps3a (s=2, t1=8 z1=64): TOC=32, unfused (z1=64 > tile)
    launch_conv<5,5,2,32,0,false>(cat3, wc3a, tmp, N, 256,64,64, 512,256, 512,32,32, 2,2, 512,0, 0);
    k_squash<<<(N*8*32*32 + 255)/256, 256>>>(tmp, buf5, N, 8,64,32,32, 512,0);
    // caps3b (t1=8 z1=32): TOC=32 + fused squash -> buf6
    launch_conv<5,5,1,32,32,false>(buf5, wc3b, buf6, N, 512,32,32, 512,0, 256,32,32, 2,2, 256,0, 8);
    // deconv w4 (t1=8 z1=32): fused parity, squash separate
    launch_deconv<0>(buf6, wdf4, b4s, tmp, N, 256, 32, 32, 256, 256, 0);
    k_squash<<<(N*8*64*64 + 255)/256, 256>>>(tmp, cat3, N, 8,32,64,64, 512,0);
    // caps w5 (t1=4 z1=32) fused -> buf9
    launch_conv<5,5,1,32,32,false>(cat3, wc5, buf9, N, 512,64,64, 512,0, 128,64,64, 2,2, 128,0, 4);
    // deconv w6 (t1=4 z1=16): fused parity + squash -> cat2 [0..64)
    launch_deconv<16>(buf9, wdf6, b6s, cat2, N, 128, 64, 64, 64, 128, 4);
    // caps w7 (t1=4 z1=16) fused -> buf12
    launch_conv<5,5,1,32,16,false>(cat2, wc7, buf12, N, 128,128,128, 128,0, 64,128,128, 2,2, 64,0, 4);
    // deconv w8 (t1=2 z1=16): fused parity + squash -> cat1 [0..32)
    launch_deconv<16>(buf12, wdf8, b8s, cat1, N, 64, 128, 128, 32, 48, 2);
    // caps w10 (t1=1 z1=16) fused squash + final norm -> out
    launch_conv<5,5,1,16,16,true>(cat1, wc10, out, N, 48,256,256, 48,0, 16,256,256, 2,2, 1,0, 1);
}

// round 14
// speedup vs baseline: 1.0186x; 1.0186x over previous
#include <cuda_runtime.h>
#include <math.h>
#include <stdint.h>
#include <stddef.h>

#define MAXN 4

// ---------------- scratch: device globals ----------------
__device__ float g_tmp  [(size_t)MAXN*32*256*256];
__device__ float g_buf1 [(size_t)MAXN*32*128*128];
__device__ float g_buf3 [(size_t)MAXN*128*64*64];
__device__ float g_buf5 [(size_t)MAXN*512*32*32];
__device__ float g_buf6 [(size_t)MAXN*256*32*32];
__device__ float g_buf9 [(size_t)MAXN*128*64*64];
__device__ float g_buf12[(size_t)MAXN*64*128*128];
__device__ float g_cat1 [(size_t)MAXN*48*256*256];
__device__ float g_cat2 [(size_t)MAXN*128*128*128];
__device__ float g_cat3 [(size_t)MAXN*512*64*64];

// conv weights, layout [cin][25][Cout]
__device__ float g_wc0 [3*25*16];
__device__ float g_wc1a[16*25*32];
__device__ float g_wc1b[32*25*64];
__device__ float g_wc2a[64*25*128];
__device__ float g_wc2b[128*25*256];
__device__ float g_wc3a[256*25*512];
__device__ float g_wc3b[512*25*256];
__device__ float g_wc5 [512*25*128];
__device__ float g_wc7 [128*25*64];
__device__ float g_wc10[48*25*16];
// fused deconv weights: [Cin][25 taps][Cout]
__device__ float g_wdf4[256*25*256];
__device__ float g_wdf6[128*25*64];
__device__ float g_wdf8[64*25*32];
__device__ float g_b4s[256];
__device__ float g_b6s[64];
__device__ float g_b8s[32];

// ---------------- helpers ----------------
__device__ __forceinline__ unsigned long long pack2(float a, float b)
{
    unsigned long long r;
    asm("mov.b64 %0, {%1, %2};" : "=l"(r) : "r"(__float_as_uint(a)), "r"(__float_as_uint(b)));
    return r;
}
__device__ __forceinline__ void ffma2(unsigned long long& d, unsigned long long a, unsigned long long b)
{
    asm("fma.rn.f32x2 %0, %1, %2, %0;" : "+l"(d) : "l"(a), "l"(b));
}
__device__ __forceinline__ float2 unpack2(unsigned long long v)
{
    unsigned int lo, hi;
    asm("mov.b64 {%0, %1}, %2;" : "=r"(lo), "=r"(hi) : "l"(v));
    float2 f; f.x = __uint_as_float(lo); f.y = __uint_as_float(hi);
    return f;
}
__device__ __forceinline__ uint32_t saddr(const void* p)
{
    return (uint32_t)__cvta_generic_to_shared(p);
}
__device__ __forceinline__ void cpa4(uint32_t dst, const float* src, bool ok)
{
    int sz = ok ? 4 : 0;
    asm volatile("cp.async.ca.shared.global [%0], [%1], 4, %2;" :: "r"(dst), "l"(src), "r"(sz) : "memory");
}
__device__ __forceinline__ void cpa16(uint32_t dst, const float* src, bool ok)
{
    int sz = ok ? 16 : 0;
    asm volatile("cp.async.cg.shared.global [%0], [%1], 16, %2;" :: "r"(dst), "l"(src), "r"(sz) : "memory");
}
#define CP_COMMIT() asm volatile("cp.async.commit_group;" ::: "memory")
#define CP_WAIT0()  asm volatile("cp.async.wait_group 0;" ::: "memory")

__device__ __forceinline__ float route_f(int oh, int ow, int H, int W, float t1, float s2)
{
    int rlo = oh - 2 > 0 ? oh - 2 : 0;
    int rhi = oh + 2 < H - 1 ? oh + 2 : H - 1;
    int clo = ow - 2 > 0 ? ow - 2 : 0;
    int chi = ow + 2 < W - 1 ? ow + 2 : W - 1;
    float cnt = (float)((rhi - rlo + 1) * (chi - clo + 1));
    float r = 1.f / (t1 * cnt);
    float n2 = r * r * s2;
    return r * n2 / ((1.f + n2) * sqrtf(n2 + 1e-9f));
}

// ---------------- fused weight prep ----------------
struct PrepC {
    const float* src[10]; float* dst[10];
    int t0[10], Cout[10], z0[10];
};
__global__ void k_prep_conv(PrepC a)
{
    int task = blockIdx.y;
    int t0 = a.t0[task], Cout = a.Cout[task], z0 = a.z0[task];
    int total = t0 * z0 * 25 * Cout;
    int i = blockIdx.x * 256 + threadIdx.x;
    if (i >= total) return;
    int o = i % Cout; int r = i / Cout;
    int k = r % 25; r /= 25;
    int z = r % z0; int t = r / z0;
    a.dst[task][i] = a.src[task][((size_t)(t * Cout + o) * z0 + z) * 25 + k];
}

struct PrepD {
    const float* src[6]; float* dst[6];
    int Cin[6], Cout[6], t0[6], kind[6];
};
__global__ void k_prep_dec(PrepD a)
{
    int task = blockIdx.y;
    int i = blockIdx.x * 256 + threadIdx.x;
    int Cout = a.Cout[task];
    if (a.kind[task] == 1) {
        if (i >= Cout) return;
        float s = 0.f;
        for (int t = 0; t < a.t0[task]; ++t) s += a.src[task][t * Cout + i];
        a.dst[task][i] = s;
        return;
    }
    int Cin = a.Cin[task];
    int total = Cin * 25 * Cout;
    if (i >= total) return;
    int o = i % Cout; int r = i / Cout;
    int tap = r % 25; int c = r / 25;
    int ph, pw, dh, dw;
    if (tap < 9)       { ph = 0; pw = 0; dh = tap / 3 - 1;       dw = tap % 3 - 1; }
    else if (tap < 15) { int t = tap - 9;  ph = 0; pw = 1; dh = t / 2 - 1; dw = t % 2; }
    else if (tap < 21) { int t = tap - 15; ph = 1; pw = 0; dh = t / 3;     dw = t % 3 - 1; }
    else               { int t = tap - 21; ph = 1; pw = 1; dh = t / 2;     dw = t % 2; }
    int kh = 2 * (dh + (ph ? 0 : 1)) + ph;
    int kw = 2 * (dw + (pw ? 0 : 1)) + pw;
    a.dst[task][i] = a.src[task][((size_t)c * Cout + o) * 25 + (4 - kh) * 5 + (4 - kw)];
}

// ---------------- cp.async pipelined tiled conv, optional fused squash ----------------
template<int KH, int KW, int S, int TOC, int NC, int Z1, bool FINAL>
__global__ __launch_bounds__(256, (TOC >= 64) ? 1 : 2)
void conv_tiled(const float* __restrict__ x, const float* __restrict__ wgt,
                float* __restrict__ y,
                int Cin, int Hin, int Win, int CinTot, int cin0,
                int Cout, int Hout, int Wout, int padh, int padw,
                int CoutTot, int oc0, int t1i, int nOcTiles)
{
    constexpr int TW = 32, TH = 8, PIX = 8;
    constexpr int WG = 4;
    constexpr int OCT = TOC / 8;
    constexpr int NPAIR = OCT / 2;
    constexpr int XW = (TW - 1) * S + KW;
    constexpr int XH = (TH - 1) * S + KH;
    constexpr int XWP = (XW & 1) ? XW : XW + 1;
    constexpr int KK = KH * KW;
    constexpr int SPAN = (PIX - 1) * S + KW;
    constexpr int XTOT = NC * XH * XW;
    constexpr int WTOT = NC * KK * TOC;
    constexpr int XCNT = (XTOT + 255) / 256;
    constexpr int WQ   = WTOT / 4;
    constexpr int WQCNT = (WQ + 255) / 256;
    constexpr int SXSZ = 2 * NC * XH * XWP;
    static_assert(NPAIR >= 1, "need oc pairs");
    static_assert(Z1 == 0 || (Z1 % OCT == 0 && TOC % Z1 == 0), "z1 grouping");
    static_assert(Z1 == 0 || SXSZ + 2 * WTOT >= 8 * 32 * PIX, "ps overlay fits");

    __shared__ __align__(16) float smem_all[SXSZ + 2 * WTOT];

    const int tid = threadIdx.x;
    const int owg = tid % WG;
    const int ohh = (tid / WG) % TH;
    const int ocg = tid >> 5;
    const int lane = tid & 31;

    const int wt = blockIdx.x, ht = blockIdx.y;
    const int octile = blockIdx.z % nOcTiles;
    const int n      = blockIdx.z / nOcTiles;

    const int ocb = octile * TOC;
    const int oh0 = ht * TH, ow0 = wt * TW;
    const int ih0 = oh0 * S - padh;
    const int iw0 = ow0 * S - padw;
    const size_t HWin = (size_t)Hin * Win;

    const float* xn = x + ((size_t)n * CinTot + cin0) * HWin;
    const float* wb = wgt + ocb;
    const int nCh = (Cin + NC - 1) / NC;

    const uint32_t sxa = saddr(smem_all);
    const uint32_t swa = sxa + SXSZ * 4;

    unsigned long long acc[NPAIR][PIX];
    #pragma unroll
    for (int p = 0; p < NPAIR; ++p)
        #pragma unroll
        for (int i = 0; i < PIX; ++i) acc[p][i] = 0ull;

    auto issue = [&](int ch, int buf) {
        #pragma unroll
        for (int j = 0; j < XCNT; ++j) {
            int g = tid + j * 256;
            if (g < XTOT) {
                int c = g / (XH * XW), r = g % (XH * XW);
                int rr = r / XW, cc = r % XW;
                int ci = ch * NC + c;
                int hi = ih0 + rr, wi = iw0 + cc;
                bool ok = (ci < Cin) && (hi >= 0) && (hi < Hin) && (wi >= 0) && (wi < Win);
                const float* src = ok ? xn + (size_t)ci * HWin + (size_t)hi * Win + wi : xn;
                cpa4(sxa + (uint32_t)(buf * (NC * XH * XWP) + c * (XH * XWP) + rr * XWP + cc) * 4,
                     src, ok);
            }
        }
        #pragma unroll
        for (int j = 0; j < WQCNT; ++j) {
            int q = tid + j * 256;
            if (q < WQ) {
                int idx = q * 4;
                int c = idx / (KK * TOC), r = idx % (KK * TOC);
                int kk = r / TOC, oc = r % TOC;
                int ci = ch * NC + c;
                bool ok = ci < Cin;
                const float* src = ok ? wb + ((size_t)ci * KK + kk) * Cout + oc : wgt;
                cpa16(swa + (uint32_t)(buf * WTOT + idx) * 4, src, ok);
            }
        }
        CP_COMMIT();
    };

    issue(0, 0);

    const int xbase = (ohh * S) * XWP + owg * PIX * S;

    for (int ch = 0; ch < nCh; ++ch) {
        CP_WAIT0();
        __syncthreads();
        if (ch + 1 < nCh) issue(ch + 1, (ch + 1) & 1);

        const float* sxb = smem_all + (ch & 1) * (NC * XH * XWP);
        const float* swb = smem_all + SXSZ + (ch & 1) * WTOT;
        #pragma unroll 1
        for (int c = 0; c < NC; ++c) {
            const float* sxc = sxb + c * (XH * XWP);
            const float* swc = swb + c * (KK * TOC) + ocg * OCT;
            #pragma unroll
            for (int kh = 0; kh < KH; ++kh) {
                unsigned long long xd[SPAN];
                #pragma unroll
                for (int i = 0; i < SPAN; ++i) {
                    float v = sxc[xbase + kh * XWP + i];
                    xd[i] = pack2(v, v);
                }
                #pragma unroll
                for (int kw = 0; kw < KW; ++kw) {
                    const float* wp = swc + (kh * KW + kw) * TOC;
                    #pragma unroll
                    for (int pq = 0; pq < NPAIR; pq += 2) {
                        if (pq + 1 < NPAIR || (NPAIR & 1) == 0) {
                            ulonglong2 wv2 = *(const ulonglong2*)(wp + 2 * pq);
                            #pragma unroll
                            for (int i = 0; i < PIX; ++i) {
                                ffma2(acc[pq][i], xd[i * S + kw], wv2.x);
                                ffma2(acc[pq + 1][i], xd[i * S + kw], wv2.y);
                            }
                        } else {
                            unsigned long long wv = *(const unsigned long long*)(wp + 2 * pq);
                            #pragma unroll
                            for (int i = 0; i < PIX; ++i)
                                ffma2(acc[pq][i], xd[i * S + kw], wv);
                        }
                    }
                }
            }
        }
    }

    const int oh = oh0 + ohh;

    if (Z1 == 0) {
        #pragma unroll
        for (int p = 0; p < NPAIR; ++p) {
            int oca = ocb + ocg * OCT + 2 * p;
            float* y0 = y + (((size_t)n * CoutTot + oc0 + oca) * Hout + oh) * Wout;
            float* y1 = y0 + (size_t)Hout * Wout;
            #pragma unroll
            for (int i = 0; i < PIX; ++i) {
                int ow = ow0 + owg * PIX + i;
                float2 v = unpack2(acc[p][i]);
                y0[ow] = v.x;
                y1[ow] = v.y;
            }
        }
    } else {
        __syncthreads();
        float* ps = smem_all;
        #pragma unroll
        for (int i = 0; i < PIX; ++i) {
            float s = 0.f;
            #pragma unroll
            for (int p = 0; p < NPAIR; ++p) {
                float2 v = unpack2(acc[p][i]);
                s += v.x * v.x + v.y * v.y;
            }
            ps[ocg * 256 + i * 32 + lane] = s;
        }
        __syncthreads();
        constexpr int GPERZ = (Z1 > 0) ? Z1 / OCT : 1;
        const int g0 = (ocg / GPERZ) * GPERZ;
        const float t1f = (float)t1i;
        #pragma unroll
        for (int i = 0; i < PIX; ++i) {
            int ow = ow0 + owg * PIX + i;
            float s2 = 0.f;
            #pragma unroll
            for (int g = 0; g < GPERZ; ++g) s2 += ps[(g0 + g) * 256 + i * 32 + lane];
            float f = route_f(oh, ow, Hout, Wout, t1f, s2);
            if (FINAL) {
                if (ocg == 0)
                    y[((size_t)n * Hout + oh) * Wout + ow] = sqrtf(f * f * s2 + 1e-9f);
            } else {
                #pragma unroll
                for (int p = 0; p < NPAIR; ++p) {
                    int oca = ocb + ocg * OCT + 2 * p;
                    float2 v = unpack2(acc[p][i]);
                    y[(((size_t)n * CoutTot + oc0 + oca) * Hout + oh) * Wout + ow] = f * v.x;
                    y[(((size_t)n * CoutTot + oc0 + oca + 1) * Hout + oh) * Wout + ow] = f * v.y;
                }
            }
        }
    }
}

// ---------------- fused 4-parity deconv with cp.async, optional squash ----------------
template<int TOC, int Z1, int NC>
__global__ __launch_bounds__(256, 2)
void deconv_tiled(const float* __restrict__ x, const float* __restrict__ wgt,
                  const float* __restrict__ bias, float* __restrict__ y,
                  int Cin, int H, int W, int Cout, int CoutTot, int t1i, int nOcTiles)
{
    constexpr int TW = 32, TH = 8, PIX = 8;
    constexpr int WG = 4;
    constexpr int OCT = TOC / 8;
    static_assert(OCT == 2, "deconv uses OCT=2");
    constexpr int XW = TW + 2, XH = TH + 2, XWP = XW + 1;
    constexpr int XTOT = NC * XH * XW;
    constexpr int WTOT = NC * 25 * TOC;
    constexpr int XCNT = (XTOT + 255) / 256;
    constexpr int WQ   = WTOT / 4;
    constexpr int WQCNT = (WQ + 255) / 256;
    constexpr int SXSZ = 2 * NC * XH * XWP;
    constexpr int SMSZ = (SXSZ + 2 * WTOT) > 2048 ? (SXSZ + 2 * WTOT) : 2048;

    __shared__ __align__(16) float smem_all[SMSZ];

    const int tid = threadIdx.x;
    const int owg = tid % WG;
    const int ohh = (tid / WG) % TH;
    const int ocg = tid >> 5;
    const int lane = tid & 31;

    const int wt = blockIdx.x, ht = blockIdx.y;
    const int octile = blockIdx.z % nOcTiles;
    const int n      = blockIdx.z / nOcTiles;

    const int ocb = octile * TOC;
    const int oh0 = ht * TH, ow0 = wt * TW;
    const int ih0 = oh0 - 1, iw0 = ow0 - 1;
    const size_t HWin = (size_t)H * W;
    const int yH = 2 * H, yW = 2 * W;

    const int oca = ocb + ocg * OCT;
    unsigned long long bi = pack2(bias[oca], bias[oca + 1]);
    unsigned long long acc[4][PIX];
    #pragma unroll
    for (int par = 0; par < 4; ++par)
        #pragma unroll
        for (int i = 0; i < PIX; ++i) acc[par][i] = bi;

    const float* xn = x + (size_t)n * Cin * HWin;
    const float* wb = wgt + ocb;
    const int nCh = (Cin + NC - 1) / NC;

    const uint32_t sxa = saddr(smem_all);
    const uint32_t swa = sxa + SXSZ * 4;

    auto issue = [&](int ch, int buf) {
        #pragma unroll
        for (int j = 0; j < XCNT; ++j) {
            int g = tid + j * 256;
            if (g < XTOT) {
                int c = g / (XH * XW), r = g % (XH * XW);
                int rr = r / XW, cc = r % XW;
                int ci = ch * NC + c;
                int hi = ih0 + rr, wi = iw0 + cc;
                bool ok = (ci < Cin) && (hi >= 0) && (hi < H) && (wi >= 0) && (wi < W);
                const float* src = ok ? xn + (size_t)ci * HWin + (size_t)hi * W + wi : xn;
                cpa4(sxa + (uint32_t)(buf * (NC * XH * XWP) + c * (XH * XWP) + rr * XWP + cc) * 4,
                     src, ok);
            }
        }
        #pragma unroll
        for (int j = 0; j < WQCNT; ++j) {
            int q = tid + j * 256;
            if (q < WQ) {
                int idx = q * 4;
                int c = idx / (25 * TOC), r = idx % (25 * TOC);
                int tap = r / TOC, oc = r % TOC;
                int ci = ch * NC + c;
                bool ok = ci < Cin;
                const float* src = ok ? wb + ((size_t)ci * 25 + tap) * Cout + oc : wgt;
                cpa16(swa + (uint32_t)(buf * WTOT + idx) * 4, src, ok);
            }
        }
        CP_COMMIT();
    };

    issue(0, 0);

    for (int ch = 0; ch < nCh; ++ch) {
        CP_WAIT0();
        __syncthreads();
        if (ch + 1 < nCh) issue(ch + 1, (ch + 1) & 1);

        const float* sxb = smem_all + (ch & 1) * (NC * XH * XWP);
        const float* swb = smem_all + SXSZ + (ch & 1) * WTOT;
        #pragma unroll 1
        for (int c = 0; c < NC; ++c) {
            const float* sxc = sxb + c * (XH * XWP);
            const float* swc = swb + c * (25 * TOC) + ocg * OCT;
            #pragma unroll
            for (int dh = -1; dh <= 1; ++dh) {
                unsigned long long xd[PIX + 2];
                const int rbase = (ohh + 1 + dh) * XWP + owg * PIX;
                #pragma unroll
                for (int j = 0; j < PIX + 2; ++j) {
                    float v = sxc[rbase + j];
                    xd[j] = pack2(v, v);
                }
                #pragma unroll
                for (int dw = -1; dw <= 1; ++dw) {
                    unsigned long long wv = *(const unsigned long long*)
                        (swc + ((dh + 1) * 3 + (dw + 1)) * TOC);
                    #pragma unroll
                    for (int i = 0; i < PIX; ++i)
                        ffma2(acc[0][i], xd[i + dw + 1], wv);
                }
                #pragma unroll
                for (int dw = 0; dw <= 1; ++dw) {
                    unsigned long long wv = *(const unsigned long long*)
                        (swc + (9 + (dh + 1) * 2 + dw) * TOC);
                    #pragma unroll
                    for (int i = 0; i < PIX; ++i)
                        ffma2(acc[1][i], xd[i + dw + 1], wv);
                }
                if (dh >= 0) {
                    #pragma unroll
                    for (int dw = -1; dw <= 1; ++dw) {
                        unsigned long long wv = *(const unsigned long long*)
                            (swc + (15 + dh * 3 + (dw + 1)) * TOC);
                        #pragma unroll
                        for (int i = 0; i < PIX; ++i)
                            ffma2(acc[2][i], xd[i + dw + 1], wv);
                    }
                    #pragma unroll
                    for (int dw = 0; dw <= 1; ++dw) {
                        unsigned long long wv = *(const unsigned long long*)
                            (swc + (21 + dh * 2 + dw) * TOC);
                        #pragma unroll
                        for (int i = 0; i < PIX; ++i)
                            ffma2(acc[3][i], xd[i + dw + 1], wv);
                    }
                }
            }
        }
    }

    if (Z1 == 0) {
        #pragma unroll
        for (int par = 0; par < 4; ++par) {
            const int ph = par >> 1, pw = par & 1;
            const int oh = 2 * (oh0 + ohh) + ph;
            float* y0 = y + (((size_t)n * CoutTot + oca) * yH + oh) * yW;
            float* y1 = y0 + (size_t)yH * yW;
            #pragma unroll
            for (int i = 0; i < PIX; ++i) {
                int ow = 2 * (ow0 + owg * PIX + i) + pw;
                float2 v = unpack2(acc[par][i]);
                y0[ow] = v.x;
                y1[ow] = v.y;
            }
        }
    } else {
        static_assert(Z1 == 0 || Z1 == TOC, "deconv squash: one group per tile");
        __syncthreads();
        float* ps = smem_all;
        const float t1f = (float)t1i;
        #pragma unroll 1
        for (int par = 0; par < 4; ++par) {
            const int ph = par >> 1, pw = par & 1;
            const int oh = 2 * (oh0 + ohh) + ph;
            #pragma unroll
            for (int i = 0; i < PIX; ++i) {
                float2 v = unpack2(acc[par][i]);
                ps[ocg * 256 + i * 32 + lane] = v.x * v.x + v.y * v.y;
            }
            __syncthreads();
            #pragma unroll
            for (int i = 0; i < PIX; ++i) {
                int ow = 2 * (ow0 + owg * PIX + i) + pw;
                float s2 = 0.f;
                #pragma unroll
                for (int g = 0; g < 8; ++g) s2 += ps[g * 256 + i * 32 + lane];
                float f = route_f(oh, ow, yH, yW, t1f, s2);
                float2 v = unpack2(acc[par][i]);
                y[(((size_t)n * CoutTot + oca) * yH + oh) * yW + ow] = f * v.x;
                y[(((size_t)n * CoutTot + oca + 1) * yH + oh) * yW + ow] = f * v.y;
            }
            __syncthreads();
        }
    }
}

// ---------------- standalone squash (z1 > tile) ----------------
__global__ void k_squash(const float* __restrict__ x, float* __restrict__ y,
                         int N, int t1, int z1, int H, int W, int CoutTot, int ch0)
{
    int idx = blockIdx.x * blockDim.x + threadIdx.x;
    int total = N * t1 * H * W;
    if (idx >= total) return;
    int w = idx % W; int t = idx / W;
    int h = t % H;   t /= H;
    int tt = t % t1; int n = t / t1;

    size_t HW = (size_t)H * W;
    const float* xp = x + ((size_t)(n * t1 + tt) * z1) * HW + (size_t)h * W + w;
    float s2 = 0.f;
    for (int c = 0; c < z1; ++c) { float v = xp[c * HW]; s2 += v * v; }
    float f = route_f(h, w, H, W, (float)t1, s2);
    float* yp = y + ((size_t)n * CoutTot + ch0 + tt * z1) * HW + (size_t)h * W + w;
    for (int c = 0; c < z1; ++c) yp[c * HW] = f * xp[c * HW];
}

// ---------------- host dispatch ----------------
template<int KH, int KW, int S, int TOC, int Z1, bool FINAL>
static void launch_conv(const float* x, const float* w, float* y,
                        int N, int Cin, int Hin, int Win, int CinTot, int cin0,
                        int Cout, int Hout, int Wout, int padh, int padw,
                        int CoutTot, int oc0, int t1)
{
    constexpr int NC = (S == 2) ? 2 : 4;
    int nOcT = (Cout + TOC - 1) / TOC;
    dim3 grid((Wout + 31) / 32, (Hout + 7) / 8, N * nOcT);
    conv_tiled<KH, KW, S, TOC, NC, Z1, FINAL><<<grid, 256>>>(
        x, w, y, Cin, Hin, Win, CinTot, cin0,
        Cout, Hout, Wout, padh, padw, CoutTot, oc0, t1, nOcT);
}

template<int Z1>
static void launch_deconv(const float* x, const float* w, const float* b, float* y,
                          int N, int Cin, int H, int W, int Cout, int CoutTot, int t1)
{
    constexpr int TOC = 16;
    int nOcT = Cout / TOC;
    dim3 grid(W / 32, H / 8, N * nOcT);
    deconv_tiled<TOC, Z1, 4><<<grid, 256>>>(x, w, b, y, Cin, H, W, Cout, CoutTot, t1, nOcT);
}

static float* sym(const void* s)
{
    void* p = nullptr;
    cudaGetSymbolAddress(&p, (const void*)s);
    return (float*)p;
}

extern "C" void kernel_launch(void* const* d_in, const int* in_sizes, int n_in,
                              void* d_out, int out_size)
{
    const float* x    = (const float*)d_in[0];
    const float* w0   = (const float*)d_in[1];
    const float* w1a  = (const float*)d_in[2];
    const float* w1b  = (const float*)d_in[3];
    const float* w2a  = (const float*)d_in[4];
    const float* w2b  = (const float*)d_in[5];
    const float* w3a  = (const float*)d_in[6];
    const float* w3b  = (const float*)d_in[7];
    const float* w4   = (const float*)d_in[8];
    const float* b4   = (const float*)d_in[9];
    const float* w5   = (const float*)d_in[10];
    const float* w6   = (const float*)d_in[11];
    const float* b6   = (const float*)d_in[12];
    const float* w7   = (const float*)d_in[13];
    const float* w8   = (const float*)d_in[14];
    const float* b8   = (const float*)d_in[15];
    const float* w10  = (const float*)d_in[16];
    float* out = (float*)d_out;
    (void)n_in; (void)out_size;

    const int N = in_sizes[0] / (3 * 256 * 256);

    float* tmp   = sym(&g_tmp);
    float* buf1  = sym(&g_buf1);
    float* buf3  = sym(&g_buf3);
    float* buf5  = sym(&g_buf5);
    float* buf6  = sym(&g_buf6);
    float* buf9  = sym(&g_buf9);
    float* buf12 = sym(&g_buf12);
    float* cat1  = sym(&g_cat1);
    float* cat2  = sym(&g_cat2);
    float* cat3  = sym(&g_cat3);
    float* wc0   = sym(&g_wc0);
    float* wc1a  = sym(&g_wc1a);
    float* wc1b  = sym(&g_wc1b);
    float* wc2a  = sym(&g_wc2a);
    float* wc2b  = sym(&g_wc2b);
    float* wc3a  = sym(&g_wc3a);
    float* wc3b  = sym(&g_wc3b);
    float* wc5   = sym(&g_wc5);
    float* wc7   = sym(&g_wc7);
    float* wc10  = sym(&g_wc10);
    float* wdf4  = sym(&g_wdf4);
    float* wdf6  = sym(&g_wdf6);
    float* wdf8  = sym(&g_wdf8);
    float* b4s   = sym(&g_b4s);
    float* b6s   = sym(&g_b6s);
    float* b8s   = sym(&g_b8s);

    // ---- weight prep: 2 fused launches ----
    {
        PrepC pc;
        const float* srcs[10] = {w0, w1a, w1b, w2a, w2b, w3a, w3b, w5, w7, w10};
        float*       dsts[10] = {wc0, wc1a, wc1b, wc2a, wc2b, wc3a, wc3b, wc5, wc7, wc10};
        int t0s[10]   = {1, 1, 2, 4, 4, 8, 8, 16, 8, 3};
        int couts[10] = {16, 32, 64, 128, 256, 512, 256, 128, 64, 16};
        int z0s[10]   = {3, 16, 16, 16, 32, 32, 64, 32, 16, 16};
        int maxTot = 0;
        for (int i = 0; i < 10; ++i) {
            pc.src[i] = srcs[i]; pc.dst[i] = dsts[i];
            pc.t0[i] = t0s[i]; pc.Cout[i] = couts[i]; pc.z0[i] = z0s[i];
            int tot = t0s[i] * couts[i] * z0s[i] * 25;
            if (tot > maxTot) maxTot = tot;
        }
        dim3 g((maxTot + 255) / 256, 10);
        k_prep_conv<<<g, 256>>>(pc);
    }
    {
        PrepD pd;
        const float* wsrc[3] = {w4, w6, w8};
        float*       wdst[3] = {wdf4, wdf6, wdf8};
        int cins[3]  = {256, 128, 64};
        int couts[3] = {256, 64, 32};
        int t0s[3]   = {8, 4, 4};
        const float* bsrc[3] = {b4, b6, b8};
        float*       bdst[3] = {b4s, b6s, b8s};
        int maxTot = 0;
        for (int d = 0; d < 3; ++d) {
            pd.src[d] = wsrc[d]; pd.dst[d] = wdst[d];
            pd.Cin[d] = cins[d]; pd.Cout[d] = couts[d]; pd.t0[d] = t0s[d]; pd.kind[d] = 0;
            int tot = cins[d] * 25 * couts[d];
            if (tot > maxTot) maxTot = tot;
            pd.src[3 + d] = bsrc[d]; pd.dst[3 + d] = bdst[d];
            pd.Cin[3 + d] = 0; pd.Cout[3 + d] = couts[d]; pd.t0[3 + d] = t0s[d]; pd.kind[3 + d] = 1;
        }
        dim3 g((maxTot + 255) / 256, 6);
        k_prep_dec<<<g, 256>>>(pd);
    }

    // ---- forward pass (R13 base; caps3a now TOC=64 with fused squash) ----
    // conv1 -> cat1 [32..48)  (skip1, raw)
    launch_conv<5,5,1,16,0,false>(x, wc0, cat1, N, 3,256,256, 3,0, 16,256,256, 2,2, 48,32, 0);
    // caps1a (s=2, t1=2 z1=16) fused squash -> buf1
    launch_conv<5,5,2,32,16,false>(cat1, wc1a, buf1, N, 16,256,256, 48,32, 32,128,128, 2,2, 32,0, 2);
    // caps1b (t1=4 z1=16) fused -> cat2 [64..128)
    launch_conv<5,5,1,32,16,false>(buf1, wc1b, cat2, N, 32,128,128, 32,0, 64,128,128, 2,2, 128,64, 4);
    // caps2a (s=2, t1=4 z1=32) fused -> buf3
    launch_conv<5,5,2,32,32,false>(cat2, wc2a, buf3, N, 64,128,128, 128,64, 128,64,64, 2,2, 128,0, 4);
    // caps2b (t1=8 z1=32) fused -> cat3 [256..512)
    launch_conv<5,5,1,32,32,false>(buf3, wc2b, cat3, N, 128,64,64, 128,0, 256,64,64, 2,2, 512,256, 8);
    // caps3a (s=2, t1=8 z1=64): TOC=64 (full z1 group per tile) + fused squash -> buf5
    launch_conv<5,5,2,64,64,false>(cat3, wc3a, buf5, N, 256,64,64, 512,256, 512,32,32, 2,2, 512,0, 8);
    // caps3b (t1=8 z1=32): TOC=32 + fused squash -> buf6
    launch_conv<5,5,1,32,32,false>(buf5, wc3b, buf6, N, 512,32,32, 512,0, 256,32,32, 2,2, 256,0, 8);
    // deconv w4 (t1=8 z1=32): fused parity, squash separate
    launch_deconv<0>(buf6, wdf4, b4s, tmp, N, 256, 32, 32, 256, 256, 0);
    k_squash<<<(N*8*64*64 + 255)/256, 256>>>(tmp, cat3, N, 8,32,64,64, 512,0);
    // caps w5 (t1=4 z1=32) fused -> buf9
    launch_conv<5,5,1,32,32,false>(cat3, wc5, buf9, N, 512,64,64, 512,0, 128,64,64, 2,2, 128,0, 4);
    // deconv w6 (t1=4 z1=16): fused parity + squash -> cat2 [0..64)
    launch_deconv<16>(buf9, wdf6, b6s, cat2, N, 128, 64, 64, 64, 128, 4);
    // caps w7 (t1=4 z1=16) fused -> buf12
    launch_conv<5,5,1,32,16,false>(cat2, wc7, buf12, N, 128,128,128, 128,0, 64,128,128, 2,2, 64,0, 4);
    // deconv w8 (t1=2 z1=16): fused parity + squash -> cat1 [0..32)
    launch_deconv<16>(buf12, wdf8, b8s, cat1, N, 64, 128, 128, 32, 48, 2);
    // caps w10 (t1=1 z1=16) fused squash + final norm -> out
    launch_conv<5,5,1,16,16,true>(cat1, wc10, out, N, 48,256,256, 48,0, 16,256,256, 2,2, 1,0, 1);
}